// round 13
// baseline (speedup 1.0000x reference)
#include <cuda_runtime.h>
#include <cuda_bf16.h>

// Problem constants
#define SEQ_LEN 512
#define EMBED_DIM 768
#define MAX_SPAN_LEN 16
#define WIDTH_EMB 50
#define NUM_LABELS 9
#define N_SPANS 32768
#define W_COLS (3 * EMBED_DIM + WIDTH_EMB)   // 2354

#define PSTRIDE 12            // padded table row: 9 floats in 12 -> 48B, 16B aligned
#define K2 (EMBED_DIM / 2)    // 384 float2 per 768-block row

#define NBLK 144              // <= SM count -> all blocks resident
#define TPB 512

#define SPANS_PER_BLK 228     // 143*228+164 = 32768

// Scratch tables crossing the grid barrier (device globals; no allocation)
__device__ float g_ps[SEQ_LEN * PSTRIDE];
__device__ float g_pe[SEQ_LEN * PSTRIDE];
__device__ float g_pa[SEQ_LEN * PSTRIDE];
__device__ unsigned long long g_bar;   // monotonic grid barrier (never reset)

__device__ __forceinline__ void grid_sync() {
    __syncthreads();
    if (threadIdx.x == 0) {
        __threadfence();                                   // release our writes
        unsigned long long old = atomicAdd(&g_bar, 1ULL);
        unsigned long long target = (old / NBLK + 1ULL) * (unsigned long long)NBLK;
        while (*(volatile unsigned long long*)&g_bar < target)
            __nanosleep(32);
        __threadfence();                                   // acquire others' writes
    }
    __syncthreads();
}

// Fixed (disjoint) dynamic smem layout, in floats:
//  [0, 5376)                wsA: phase A W tile, 7 rows x 384 float2 (21.5 KB)
//  [5376, 11520)            tps   (1536 float4)
//  [11520, 17664)           tpe   (1536 float4)
//  [17664, 23824)           tpacs (513 rows x 12 + pad)
//  [23824, 24032)           tpw   (17 rows x 12 + pad)
//  [24032, 24064)           sinv
//  [24064, 26116)           so    (SPANS_PER_BLK * 9)
#define OFF_WSA   0
#define OFF_TPS   5376
#define OFF_TPE   11520
#define OFF_TPACS 17664
#define OFF_TPW   23824
#define OFF_SINV  24032
#define OFF_SO    24064
#define SMEM_FLOATS 26116
#define SMEM_BYTES (SMEM_FLOATS * 4)
#define NT4 1536

// ---------------------------------------------------------------------------
// Phase A body: one (token-group, output-group) item per block.
// 15 warps = 15 tokens (warp-per-token), warp 15 helps fill only.
// ONUM outputs staged in smem; all W offsets compile-time.
// ---------------------------------------------------------------------------
template <int OBASE, int ONUM>
__device__ __forceinline__ void proj_body(const float* __restrict__ seq,
                                          const float* __restrict__ W,
                                          float2* __restrict__ wsA,
                                          int tg, int warp, int lane) {
    const int t = min(tg * 15 + warp, SEQ_LEN - 1);   // clamp: duplicate = benign

    const float2* __restrict__ w2 = (const float2*)W;     // rows 8B-aligned
    const float2* __restrict__ s2 = (const float2*)(seq + (size_t)t * EMBED_DIM);

    // prefetch this token's seq row (12 independent coalesced LDG.64)
    float2 sv[12];
    #pragma unroll
    for (int kk = 0; kk < 12; kk++) sv[kk] = s2[kk * 32 + lane];

    // cooperative fill of ONUM W rows (LDG latency overlaps the prefetch above)
    #pragma unroll
    for (int i = threadIdx.x; i < ONUM * K2; i += TPB) {
        const int oo = i / K2;
        const int j2 = i - oo * K2;
        const int o = OBASE + oo;
        const int kblk = o / 9;
        const int l = o - kblk * 9;
        wsA[i] = __ldg(w2 + l * (W_COLS / 2) + kblk * (EMBED_DIM / 2) + j2);
    }
    __syncthreads();

    if (warp < 15) {
        float acc[ONUM];
        #pragma unroll
        for (int o = 0; o < ONUM; o++) acc[o] = 0.f;

        #pragma unroll
        for (int kk = 0; kk < 12; kk++) {
            const float2 s = sv[kk];
            #pragma unroll
            for (int oo = 0; oo < ONUM; oo++) {
                const float2 wv = wsA[oo * K2 + kk * 32 + lane];
                acc[oo] = fmaf(s.x, wv.x, fmaf(s.y, wv.y, acc[oo]));
            }
        }

        #pragma unroll
        for (int oo = 0; oo < ONUM; oo++) {
            float v = acc[oo];
            #pragma unroll
            for (int off = 16; off; off >>= 1)
                v += __shfl_down_sync(0xffffffffu, v, off);
            if (lane == 0) {
                const int o = OBASE + oo;
                const int kblk = o / 9;
                const int l = o - kblk * 9;
                float* tbl = (kblk == 0) ? g_ps : (kblk == 1) ? g_pe : g_pa;
                tbl[t * PSTRIDE + l] = v;   // duplicates write identical values
            }
        }
    }
}

extern "C" __global__ void __launch_bounds__(TPB, 1)
fused_kernel(const float* __restrict__ seq,
             const int*   __restrict__ sidx,
             const int*   __restrict__ eidx,
             const int*   __restrict__ widx,
             const float* __restrict__ wtab,
             const float* __restrict__ W,
             const float* __restrict__ b,
             float* __restrict__ out) {
    extern __shared__ float smf[];
    const int tid = threadIdx.x;
    const int lane = tid & 31;
    const int warp = tid >> 5;

    // =========================== Phase A: proj ===========================
    // 144 items = 36 token-groups (15 tokens) x 4 output-groups {7,7,7,6}.
    {
        const int tg = blockIdx.x >> 2;
        float2* wsA = (float2*)(smf + OFF_WSA);
        switch (blockIdx.x & 3) {
            case 0: proj_body<0, 7>(seq, W, wsA, tg, warp, lane); break;
            case 1: proj_body<7, 7>(seq, W, wsA, tg, warp, lane); break;
            case 2: proj_body<14, 7>(seq, W, wsA, tg, warp, lane); break;
            default: proj_body<21, 6>(seq, W, wsA, tg, warp, lane); break;
        }
    }
    __syncthreads();

    // ============ Pre-sync: sync-independent phase C preludes ============
    float* tpw  = smf + OFF_TPW;
    float* sinv = smf + OFF_SINV;
    const int base = blockIdx.x * SPANS_PER_BLK;
    const int count = (N_SPANS - base < SPANS_PER_BLK) ? (N_SPANS - base)
                                                       : SPANS_PER_BLK;
    // span indices (L2 latency hides under the LUT compute / barrier wait)
    int s = 0, e = 0, w = 1;
    if (tid < count) {
        s = sidx[base + tid];
        e = eidx[base + tid];
        w = widx[base + tid];
    }
    // pw[w][l] = b[l] + width_table[w] . W[l, 2304:2354]; invw LUT
    if (tid < (MAX_SPAN_LEN + 1) * NUM_LABELS) {
        const int ww = tid / NUM_LABELS;
        const int l = tid - ww * NUM_LABELS;
        const float* wrow = W + (size_t)l * W_COLS + 3 * EMBED_DIM;
        const float* wt = wtab + ww * WIDTH_EMB;
        float acc = b[l];
        #pragma unroll
        for (int j = 0; j < WIDTH_EMB; j++)
            acc = fmaf(wt[j], wrow[j], acc);
        tpw[ww * PSTRIDE + l] = acc;
    }
    if (tid >= 160 && tid <= 160 + MAX_SPAN_LEN) {
        const int ww = tid - 160;
        sinv[ww] = 1.0f / (float)(ww < 1 ? 1 : ww);
    }

    grid_sync();   // the ONLY grid-wide barrier

    // ============ Phase C: fill + scan + span compute ============
    {
        float4* tps   = (float4*)(smf + OFF_TPS);
        float4* tpe   = (float4*)(smf + OFF_TPE);
        float*  tpacs = smf + OFF_TPACS;
        float*  so    = smf + OFF_SO;

        // cooperative fill: ps, pe, raw pa (into tpacs; scanned in place)
        const float4* gps = (const float4*)g_ps;
        const float4* gpe = (const float4*)g_pe;
        const float4* gpa = (const float4*)g_pa;
        float4* tpacs4 = (float4*)tpacs;
        #pragma unroll
        for (int i = tid; i < NT4; i += TPB) {
            tps[i] = gps[i];
            tpe[i] = gpe[i];
            tpacs4[i] = gpa[i];
        }
        __syncthreads();

        if (warp < NUM_LABELS) {
            // warp-per-label exclusive scan: preload all 16, then shuffle rounds
            const int l = warp;
            float v[16];
            #pragma unroll
            for (int c = 0; c < 16; c++)
                v[c] = tpacs[(c * 32 + lane) * PSTRIDE + l];
            float carry = 0.f;
            #pragma unroll
            for (int c = 0; c < 16; c++) {
                float x = v[c];
                #pragma unroll
                for (int off = 1; off < 32; off <<= 1) {
                    float y = __shfl_up_sync(0xffffffffu, x, off);
                    if (lane >= off) x += y;
                }
                tpacs[(c * 32 + lane) * PSTRIDE + l] = carry + x - v[c];
                carry += __shfl_sync(0xffffffffu, x, 31);
            }
            if (lane == 0) tpacs[SEQ_LEN * PSTRIDE + l] = carry;   // grand total
        }
        __syncthreads();

        if (tid < count) {
            const float invw = sinv[w];
            const float4* ps = tps + s * 3;
            const float4* pe = tpe + e * 3;
            const float4* c0 = (const float4*)(tpacs + s * PSTRIDE);
            const float4* c1 = (const float4*)(tpacs + e * PSTRIDE);
            const float4* pw = (const float4*)(tpw + w * PSTRIDE);

            float r[12];
            #pragma unroll
            for (int q = 0; q < 3; q++) {
                const float4 a = ps[q], bb = pe[q], x0 = c0[q], x1 = c1[q], d = pw[q];
                r[q * 4 + 0] = a.x + bb.x + (x1.x - x0.x) * invw + d.x;
                r[q * 4 + 1] = a.y + bb.y + (x1.y - x0.y) * invw + d.y;
                r[q * 4 + 2] = a.z + bb.z + (x1.z - x0.z) * invw + d.z;
                r[q * 4 + 3] = a.w + bb.w + (x1.w - x0.w) * invw + d.w;
            }
            #pragma unroll
            for (int l = 0; l < NUM_LABELS; l++)
                so[tid * NUM_LABELS + l] = r[l];
        }
        __syncthreads();

        // coalesced float4 output copy
        const int nf4 = count * NUM_LABELS / 4;
        float4* ob = (float4*)(out + (size_t)base * NUM_LABELS);
        const float4* sb = (const float4*)so;
        for (int i = tid; i < nf4; i += TPB)
            ob[i] = sb[i];
    }
}

// ---------------------------------------------------------------------------
// Launcher: one kernel, one launch.
// ---------------------------------------------------------------------------
extern "C" void kernel_launch(void* const* d_in, const int* in_sizes, int n_in,
                              void* d_out, int out_size) {
    const float* seq   = (const float*)d_in[0];   // [1, 512, 768]
    const int*   sidx  = (const int*)d_in[1];     // [32768]
    const int*   eidx  = (const int*)d_in[2];     // [32768]
    const int*   widx  = (const int*)d_in[3];     // [32768]
    const float* wtab  = (const float*)d_in[4];   // [17, 50]
    const float* W     = (const float*)d_in[5];   // [9, 2354]
    const float* b     = (const float*)d_in[6];   // [9]
    float* out = (float*)d_out;                   // [32768, 9]

    cudaFuncSetAttribute(fused_kernel, cudaFuncAttributeMaxDynamicSharedMemorySize,
                         SMEM_BYTES);
    fused_kernel<<<NBLK, TPB, SMEM_BYTES>>>(seq, sidx, eidx, widx, wtab, W, b, out);
}

// round 14
// speedup vs baseline: 1.0686x; 1.0686x over previous
#include <cuda_runtime.h>
#include <cuda_bf16.h>

// Problem constants
#define SEQ_LEN 512
#define EMBED_DIM 768
#define MAX_SPAN_LEN 16
#define WIDTH_EMB 50
#define NUM_LABELS 9
#define N_SPANS 32768
#define W_COLS (3 * EMBED_DIM + WIDTH_EMB)   // 2354

#define PSTRIDE 12            // padded table row: 9 floats in 12 -> 48B, 16B aligned
#define K2 (EMBED_DIM / 2)    // 384 float2 per 768-block row

#define NBLK 144              // <= SM count -> all blocks resident
#define TPB 512

#define SPANS_PER_BLK 228     // 143*228+164 = 32768

// Scratch tables crossing the grid barrier (device globals; no allocation)
__device__ float g_ps[SEQ_LEN * PSTRIDE];
__device__ float g_pe[SEQ_LEN * PSTRIDE];
__device__ float g_pa[SEQ_LEN * PSTRIDE];
__device__ unsigned long long g_bar;   // monotonic grid barrier (never reset)

__device__ __forceinline__ void grid_sync() {
    __syncthreads();
    if (threadIdx.x == 0) {
        __threadfence();                                   // release our writes
        unsigned long long old = atomicAdd(&g_bar, 1ULL);
        unsigned long long target = (old / NBLK + 1ULL) * (unsigned long long)NBLK;
        while (*(volatile unsigned long long*)&g_bar < target)
            __nanosleep(32);
        __threadfence();                                   // acquire others' writes
    }
    __syncthreads();
}

// Disjoint dynamic smem layout, in floats:
//  [0, 4608)        wsA: phase A, 2 halves x 3 rows x 384 float2   (18 KB)
//  [4608, 10768)    tpacs: 513 rows x 12 (+pad)
//  [10768, 10976)   tpw: 17 rows x 12 (+pad)
//  [10976, 11008)   sinv
//  [11008, 13060)   so: SPANS_PER_BLK * 9
#define OFF_WSA   0
#define OFF_TPACS 4608
#define OFF_TPW   10768
#define OFF_SINV  10976
#define OFF_SO    11008
#define SMEM_FLOATS 13060
#define SMEM_BYTES (SMEM_FLOATS * 4)
#define NT4 1536

extern "C" __global__ void __launch_bounds__(TPB, 1)
fused_kernel(const float* __restrict__ seq,
             const int*   __restrict__ sidx,
             const int*   __restrict__ eidx,
             const int*   __restrict__ widx,
             const float* __restrict__ wtab,
             const float* __restrict__ W,
             const float* __restrict__ b,
             float* __restrict__ out) {
    extern __shared__ float smf[];
    const int tid = threadIdx.x;
    const int lane = tid & 31;
    const int warp = tid >> 5;

    // =========================== Phase A: proj ===========================
    // 288 (token-group x output-group) items, 2 per block (one per 256-half).
    // Warp = 2 tokens sharing each wv read (halves LDS traffic).
    {
        const int half = tid >> 8;
        const int tid256 = tid & 255;
        const int wl = tid256 >> 5;
        const int item = blockIdx.x * 2 + half;    // [0, 288)
        const int tg = item / 9;
        const int og = item - tg * 9;              // 3 outputs per item
        const int t0 = tg * 16 + wl * 2;

        float2* ws = ((float2*)(smf + OFF_WSA)) + half * (3 * K2);
        const float2* __restrict__ w2 = (const float2*)W;   // rows 8B-aligned
        const float2* __restrict__ s2a = (const float2*)(seq + (size_t)t0 * EMBED_DIM);
        const float2* __restrict__ s2b = (const float2*)(seq + (size_t)(t0 + 1) * EMBED_DIM);

        // prefetch both tokens' seq rows (24 independent coalesced LDG.64)
        float2 sv0[12], sv1[12];
        #pragma unroll
        for (int kk = 0; kk < 12; kk++) sv0[kk] = s2a[kk * 32 + lane];
        #pragma unroll
        for (int kk = 0; kk < 12; kk++) sv1[kk] = s2b[kk * 32 + lane];

        // cooperative fill of this half's 3 W rows (LDG latency overlaps above)
        #pragma unroll
        for (int i = tid256; i < 3 * K2; i += 256) {
            const int oo = i / K2;
            const int j2 = i - oo * K2;
            const int o = og * 3 + oo;
            const int kblk = (o >= 18) ? 2 : (o >= 9 ? 1 : 0);
            const int l = o - kblk * 9;
            ws[i] = __ldg(w2 + l * (W_COLS / 2) + kblk * (EMBED_DIM / 2) + j2);
        }
        __syncthreads();

        float acc0[3], acc1[3];
        #pragma unroll
        for (int o = 0; o < 3; o++) { acc0[o] = 0.f; acc1[o] = 0.f; }

        #pragma unroll
        for (int kk = 0; kk < 12; kk++) {
            const float2 s0 = sv0[kk];
            const float2 s1 = sv1[kk];
            #pragma unroll
            for (int oo = 0; oo < 3; oo++) {
                const float2 wv = ws[oo * K2 + kk * 32 + lane];
                acc0[oo] = fmaf(s0.x, wv.x, fmaf(s0.y, wv.y, acc0[oo]));
                acc1[oo] = fmaf(s1.x, wv.x, fmaf(s1.y, wv.y, acc1[oo]));
            }
        }

        #pragma unroll
        for (int oo = 0; oo < 3; oo++) {
            float v0 = acc0[oo], v1 = acc1[oo];
            #pragma unroll
            for (int off = 16; off; off >>= 1) {
                v0 += __shfl_down_sync(0xffffffffu, v0, off);
                v1 += __shfl_down_sync(0xffffffffu, v1, off);
            }
            if (lane == 0) {
                const int o = og * 3 + oo;
                const int kblk = (o >= 18) ? 2 : (o >= 9 ? 1 : 0);
                const int l = o - kblk * 9;
                float* tbl = (kblk == 0) ? g_ps : (kblk == 1) ? g_pe : g_pa;
                tbl[t0 * PSTRIDE + l] = v0;
                tbl[(t0 + 1) * PSTRIDE + l] = v1;
            }
        }
    }

    // ============ Pre-sync: sync-independent phase C preludes ============
    // (disjoint smem regions; barrier inside grid_sync orders everything)
    float* tpw  = smf + OFF_TPW;
    float* sinv = smf + OFF_SINV;
    const int base = blockIdx.x * SPANS_PER_BLK;
    const int count = (N_SPANS - base < SPANS_PER_BLK) ? (N_SPANS - base)
                                                       : SPANS_PER_BLK;
    int s = 0, e = 0, w = 1;
    if (tid < count) {
        s = sidx[base + tid];
        e = eidx[base + tid];
        w = widx[base + tid];
    }
    if (tid < (MAX_SPAN_LEN + 1) * NUM_LABELS) {
        const int ww = tid / NUM_LABELS;
        const int l = tid - ww * NUM_LABELS;
        const float* wrow = W + (size_t)l * W_COLS + 3 * EMBED_DIM;
        const float* wt = wtab + ww * WIDTH_EMB;
        float acc = b[l];
        #pragma unroll
        for (int j = 0; j < WIDTH_EMB; j++)
            acc = fmaf(wt[j], wrow[j], acc);
        tpw[ww * PSTRIDE + l] = acc;
    }
    if (tid >= 160 && tid <= 160 + MAX_SPAN_LEN) {
        const int ww = tid - 160;
        sinv[ww] = 1.0f / (float)(ww < 1 ? 1 : ww);
    }

    grid_sync();   // the ONLY grid-wide barrier

    // ============ Phase C: pa fill + scan + span compute ============
    {
        float* tpacs = smf + OFF_TPACS;
        float* so    = smf + OFF_SO;

        // stage ONLY raw pa (scanned in place). ps/pe are gathered via LDG
        // (24 KB tables -> L1-resident after first touches).
        const float4* gpa = (const float4*)g_pa;
        float4* tpacs4 = (float4*)tpacs;
        #pragma unroll
        for (int i = tid; i < NT4; i += TPB)
            tpacs4[i] = gpa[i];
        __syncthreads();

        if (warp < NUM_LABELS) {
            // warp-per-label exclusive scan: preload all 16, then shuffle rounds
            const int l = warp;
            float v[16];
            #pragma unroll
            for (int c = 0; c < 16; c++)
                v[c] = tpacs[(c * 32 + lane) * PSTRIDE + l];
            float carry = 0.f;
            #pragma unroll
            for (int c = 0; c < 16; c++) {
                float x = v[c];
                #pragma unroll
                for (int off = 1; off < 32; off <<= 1) {
                    float y = __shfl_up_sync(0xffffffffu, x, off);
                    if (lane >= off) x += y;
                }
                tpacs[(c * 32 + lane) * PSTRIDE + l] = carry + x - v[c];
                carry += __shfl_sync(0xffffffffu, x, 31);
            }
            if (lane == 0) tpacs[SEQ_LEN * PSTRIDE + l] = carry;   // grand total
        }
        __syncthreads();

        if (tid < count) {
            const float invw = sinv[w];
            const float4* ps = (const float4*)(g_ps + s * PSTRIDE);  // LDG gather
            const float4* pe = (const float4*)(g_pe + e * PSTRIDE);  // LDG gather
            const float4* c0 = (const float4*)(tpacs + s * PSTRIDE);
            const float4* c1 = (const float4*)(tpacs + e * PSTRIDE);
            const float4* pw = (const float4*)(tpw + w * PSTRIDE);

            float r[12];
            #pragma unroll
            for (int q = 0; q < 3; q++) {
                const float4 a = ps[q], bb = pe[q], x0 = c0[q], x1 = c1[q], d = pw[q];
                r[q * 4 + 0] = a.x + bb.x + (x1.x - x0.x) * invw + d.x;
                r[q * 4 + 1] = a.y + bb.y + (x1.y - x0.y) * invw + d.y;
                r[q * 4 + 2] = a.z + bb.z + (x1.z - x0.z) * invw + d.z;
                r[q * 4 + 3] = a.w + bb.w + (x1.w - x0.w) * invw + d.w;
            }
            #pragma unroll
            for (int l = 0; l < NUM_LABELS; l++)
                so[tid * NUM_LABELS + l] = r[l];
        }
        __syncthreads();

        // coalesced float4 output copy
        const int nf4 = count * NUM_LABELS / 4;
        float4* ob = (float4*)(out + (size_t)base * NUM_LABELS);
        const float4* sb = (const float4*)so;
        for (int i = tid; i < nf4; i += TPB)
            ob[i] = sb[i];
    }
}

// ---------------------------------------------------------------------------
// Launcher: one kernel, one launch.
// ---------------------------------------------------------------------------
extern "C" void kernel_launch(void* const* d_in, const int* in_sizes, int n_in,
                              void* d_out, int out_size) {
    const float* seq   = (const float*)d_in[0];   // [1, 512, 768]
    const int*   sidx  = (const int*)d_in[1];     // [32768]
    const int*   eidx  = (const int*)d_in[2];     // [32768]
    const int*   widx  = (const int*)d_in[3];     // [32768]
    const float* wtab  = (const float*)d_in[4];   // [17, 50]
    const float* W     = (const float*)d_in[5];   // [9, 2354]
    const float* b     = (const float*)d_in[6];   // [9]
    float* out = (float*)d_out;                   // [32768, 9]

    cudaFuncSetAttribute(fused_kernel, cudaFuncAttributeMaxDynamicSharedMemorySize,
                         SMEM_BYTES);
    fused_kernel<<<NBLK, TPB, SMEM_BYTES>>>(seq, sidx, eidx, widx, wtab, W, b, out);
}

// round 16
// speedup vs baseline: 1.0900x; 1.0200x over previous
#include <cuda_runtime.h>
#include <cuda_bf16.h>

// Problem constants
#define SEQ_LEN 512
#define EMBED_DIM 768
#define MAX_SPAN_LEN 16
#define WIDTH_EMB 50
#define NUM_LABELS 9
#define N_SPANS 32768
#define W_COLS (3 * EMBED_DIM + WIDTH_EMB)   // 2354

#define PSTRIDE 12            // padded table row: 9 floats in 12 -> 48B, 16B aligned
#define K2 (EMBED_DIM / 2)    // 384 float2 per 768-block row

#define NBLK 144              // <= SM count -> all blocks resident
#define TPB 512

#define SPANS_PER_BLK 228     // 143*228+164 = 32768

// Scratch tables crossing the grid barrier (device globals; no allocation)
__device__ float g_ps[SEQ_LEN * PSTRIDE];
__device__ float g_pe[SEQ_LEN * PSTRIDE];
__device__ float g_pa[SEQ_LEN * PSTRIDE];
__device__ unsigned long long g_bar;   // monotonic grid barrier (never reset)

__device__ __forceinline__ void grid_sync() {
    __syncthreads();
    if (threadIdx.x == 0) {
        __threadfence();                                   // release our writes
        unsigned long long old = atomicAdd(&g_bar, 1ULL);
        unsigned long long target = (old / NBLK + 1ULL) * (unsigned long long)NBLK;
        while (*(volatile unsigned long long*)&g_bar < target)
            __nanosleep(32);
        __threadfence();                                   // acquire others' writes
    }
    __syncthreads();
}

// Disjoint dynamic smem layout, in floats:
//  [0, 4608)        wsA: phase A, 2 halves x 3 rows x 384 float2   (18 KB)
//  [4608, 10768)    tpacs: 513 rows x 12 (+pad)
//  [10768, 10976)   tpw: 17 rows x 12 (+pad)
//  [10976, 11008)   sinv
//  [11008, 11152)   ctot: 9 labels x 16 chunk totals
//  [11152, 11296)   coff: 9 labels x 16 chunk exclusive offsets
#define OFF_WSA   0
#define OFF_TPACS 4608
#define OFF_TPW   10768
#define OFF_SINV  10976
#define OFF_CTOT  11008
#define OFF_COFF  11152
#define SMEM_FLOATS 11296
#define SMEM_BYTES (SMEM_FLOATS * 4)
#define NT4 1536

extern "C" __global__ void __launch_bounds__(TPB, 1)
fused_kernel(const float* __restrict__ seq,
             const int*   __restrict__ sidx,
             const int*   __restrict__ eidx,
             const int*   __restrict__ widx,
             const float* __restrict__ wtab,
             const float* __restrict__ W,
             const float* __restrict__ b,
             float* __restrict__ out) {
    extern __shared__ float smf[];
    const int tid = threadIdx.x;
    const int lane = tid & 31;
    const int warp = tid >> 5;

    // =========================== Phase A: proj ===========================
    // 288 (token-group x output-group) items, 2 per block (one per 256-half).
    // Warp = 2 tokens sharing each wv read. All seq/wv accesses are 128-bit.
    {
        const int half = tid >> 8;
        const int tid256 = tid & 255;
        const int wl = tid256 >> 5;
        const int item = blockIdx.x * 2 + half;    // [0, 288)
        const int tg = item / 9;
        const int og = item - tg * 9;              // 3 outputs per item
        const int t0 = tg * 16 + wl * 2;

        float2* ws = ((float2*)(smf + OFF_WSA)) + half * (3 * K2);
        const float2* __restrict__ w2 = (const float2*)W;   // rows 8B-aligned
        const float4* __restrict__ s4a = (const float4*)(seq + (size_t)t0 * EMBED_DIM);
        const float4* __restrict__ s4b = s4a + (EMBED_DIM / 4);

        // prefetch both tokens' seq rows (12 independent coalesced LDG.128)
        float4 sv0[6], sv1[6];
        #pragma unroll
        for (int kk = 0; kk < 6; kk++) sv0[kk] = s4a[kk * 32 + lane];
        #pragma unroll
        for (int kk = 0; kk < 6; kk++) sv1[kk] = s4b[kk * 32 + lane];

        // cooperative fill of this half's 3 W rows (LDG latency overlaps above)
        #pragma unroll
        for (int i = tid256; i < 3 * K2; i += 256) {
            const int oo = i / K2;
            const int j2 = i - oo * K2;
            const int o = og * 3 + oo;
            const int kblk = (o >= 18) ? 2 : (o >= 9 ? 1 : 0);
            const int l = o - kblk * 9;
            ws[i] = __ldg(w2 + l * (W_COLS / 2) + kblk * (EMBED_DIM / 2) + j2);
        }
        __syncthreads();

        const float4* ws4 = (const float4*)ws;
        float acc0[3], acc1[3];
        #pragma unroll
        for (int o = 0; o < 3; o++) { acc0[o] = 0.f; acc1[o] = 0.f; }

        #pragma unroll
        for (int kk = 0; kk < 6; kk++) {
            const float4 s0 = sv0[kk];
            const float4 s1 = sv1[kk];
            #pragma unroll
            for (int oo = 0; oo < 3; oo++) {
                const float4 wv = ws4[oo * 192 + kk * 32 + lane];   // LDS.128
                acc0[oo] = fmaf(s0.x, wv.x, fmaf(s0.y, wv.y,
                           fmaf(s0.z, wv.z, fmaf(s0.w, wv.w, acc0[oo]))));
                acc1[oo] = fmaf(s1.x, wv.x, fmaf(s1.y, wv.y,
                           fmaf(s1.z, wv.z, fmaf(s1.w, wv.w, acc1[oo]))));
            }
        }

        #pragma unroll
        for (int oo = 0; oo < 3; oo++) {
            float v0 = acc0[oo], v1 = acc1[oo];
            #pragma unroll
            for (int off = 16; off; off >>= 1) {
                v0 += __shfl_down_sync(0xffffffffu, v0, off);
                v1 += __shfl_down_sync(0xffffffffu, v1, off);
            }
            if (lane == 0) {
                const int o = og * 3 + oo;
                const int kblk = (o >= 18) ? 2 : (o >= 9 ? 1 : 0);
                const int l = o - kblk * 9;
                float* tbl = (kblk == 0) ? g_ps : (kblk == 1) ? g_pe : g_pa;
                tbl[t0 * PSTRIDE + l] = v0;
                tbl[(t0 + 1) * PSTRIDE + l] = v1;
            }
        }
    }

    // ============ Pre-sync: sync-independent phase C preludes ============
    float* tpw  = smf + OFF_TPW;
    float* sinv = smf + OFF_SINV;
    const int base = blockIdx.x * SPANS_PER_BLK;
    const int count = (N_SPANS - base < SPANS_PER_BLK) ? (N_SPANS - base)
                                                       : SPANS_PER_BLK;
    int s = 0, e = 0, w = 1;
    if (tid < count) {
        s = sidx[base + tid];
        e = eidx[base + tid];
        w = widx[base + tid];
    }
    if (tid < (MAX_SPAN_LEN + 1) * NUM_LABELS) {
        const int ww = tid / NUM_LABELS;
        const int l = tid - ww * NUM_LABELS;
        const float* wrow = W + (size_t)l * W_COLS + 3 * EMBED_DIM;
        const float* wt = wtab + ww * WIDTH_EMB;
        float acc = b[l];
        #pragma unroll
        for (int j = 0; j < WIDTH_EMB; j++)
            acc = fmaf(wt[j], wrow[j], acc);
        tpw[ww * PSTRIDE + l] = acc;
    }
    if (tid >= 160 && tid <= 160 + MAX_SPAN_LEN) {
        const int ww = tid - 160;
        sinv[ww] = 1.0f / (float)(ww < 1 ? 1 : ww);
    }

    grid_sync();   // the ONLY grid-wide barrier

    // ============ Phase C: pa fill + two-level scan + span compute ============
    {
        float* tpacs = smf + OFF_TPACS;
        float* ctot  = smf + OFF_CTOT;
        float* coff  = smf + OFF_COFF;

        // stage raw pa (scanned in place). ps/pe gathered later via LDG.
        const float4* gpa = (const float4*)g_pa;
        float4* tpacs4 = (float4*)tpacs;
        #pragma unroll
        for (int i = tid; i < NT4; i += TPB)
            tpacs4[i] = gpa[i];
        __syncthreads();

        // ---- scan level 1: each of the 16 warps scans its 32-token chunk
        //      for all 9 labels (9 independent, pipelined shuffle scans) ----
        const int t = (warp << 5) + lane;
        float pav[12];
        {
            const float4* row = (const float4*)(tpacs + t * PSTRIDE);
            const float4 r0 = row[0], r1 = row[1], r2 = row[2];
            pav[0] = r0.x; pav[1] = r0.y; pav[2] = r0.z; pav[3] = r0.w;
            pav[4] = r1.x; pav[5] = r1.y; pav[6] = r1.z; pav[7] = r1.w;
            pav[8] = r2.x;
        }
        float excl[NUM_LABELS];
        #pragma unroll
        for (int l = 0; l < NUM_LABELS; l++) {
            float x = pav[l];
            #pragma unroll
            for (int off = 1; off < 32; off <<= 1) {
                float y = __shfl_up_sync(0xffffffffu, x, off);
                if (lane >= off) x += y;
            }
            excl[l] = x - pav[l];
            if (lane == 31) ctot[l * 16 + warp] = x;
        }
        __syncthreads();

        // ---- scan level 2: warps 0..8 scan the 16 chunk totals of label l ----
        if (warp < NUM_LABELS) {
            const int l = warp;
            float tv = (lane < 16) ? ctot[l * 16 + lane] : 0.f;
            float x = tv;
            #pragma unroll
            for (int off = 1; off < 32; off <<= 1) {
                float y = __shfl_up_sync(0xffffffffu, x, off);
                if (lane >= off) x += y;
            }
            if (lane < 16) coff[l * 16 + lane] = x - tv;
            if (lane == 15) tpacs[SEQ_LEN * PSTRIDE + l] = x;   // grand total
        }
        __syncthreads();

        // ---- apply offsets: write exclusive values back (3x STS.128,
        //      floats 9..11 are padding and may hold junk) ----
        {
            float vv[12];
            #pragma unroll
            for (int l = 0; l < NUM_LABELS; l++)
                vv[l] = coff[l * 16 + warp] + excl[l];
            vv[9] = 0.f; vv[10] = 0.f; vv[11] = 0.f;
            float4* row = (float4*)(tpacs + t * PSTRIDE);
            row[0] = make_float4(vv[0], vv[1], vv[2], vv[3]);
            row[1] = make_float4(vv[4], vv[5], vv[6], vv[7]);
            row[2] = make_float4(vv[8], vv[9], vv[10], vv[11]);
        }
        __syncthreads();

        // ---- span compute: direct global stores ----
        if (tid < count) {
            const float invw = sinv[w];
            const float4* ps = (const float4*)(g_ps + s * PSTRIDE);  // LDG gather
            const float4* pe = (const float4*)(g_pe + e * PSTRIDE);  // LDG gather
            const float4* c0 = (const float4*)(tpacs + s * PSTRIDE);
            const float4* c1 = (const float4*)(tpacs + e * PSTRIDE);
            const float4* pw = (const float4*)(tpw + w * PSTRIDE);

            float r[12];
            #pragma unroll
            for (int q = 0; q < 3; q++) {
                const float4 a = ps[q], bb = pe[q], x0 = c0[q], x1 = c1[q], d = pw[q];
                r[q * 4 + 0] = a.x + bb.x + (x1.x - x0.x) * invw + d.x;
                r[q * 4 + 1] = a.y + bb.y + (x1.y - x0.y) * invw + d.y;
                r[q * 4 + 2] = a.z + bb.z + (x1.z - x0.z) * invw + d.z;
                r[q * 4 + 3] = a.w + bb.w + (x1.w - x0.w) * invw + d.w;
            }
            float* op = out + (size_t)(base + tid) * NUM_LABELS;
            #pragma unroll
            for (int l = 0; l < NUM_LABELS; l++)
                op[l] = r[l];
        }
    }
}

// ---------------------------------------------------------------------------
// Launcher: one kernel, one launch.
// ---------------------------------------------------------------------------
extern "C" void kernel_launch(void* const* d_in, const int* in_sizes, int n_in,
                              void* d_out, int out_size) {
    const float* seq   = (const float*)d_in[0];   // [1, 512, 768]
    const int*   sidx  = (const int*)d_in[1];     // [32768]
    const int*   eidx  = (const int*)d_in[2];     // [32768]
    const int*   widx  = (const int*)d_in[3];     // [32768]
    const float* wtab  = (const float*)d_in[4];   // [17, 50]
    const float* W     = (const float*)d_in[5];   // [9, 2354]
    const float* b     = (const float*)d_in[6];   // [9]
    float* out = (float*)d_out;                   // [32768, 9]

    cudaFuncSetAttribute(fused_kernel, cudaFuncAttributeMaxDynamicSharedMemorySize,
                         SMEM_BYTES);
    fused_kernel<<<NBLK, TPB, SMEM_BYTES>>>(seq, sidx, eidx, widx, wtab, W, b, out);
}